// round 2
// baseline (speedup 1.0000x reference)
#include <cuda_runtime.h>
#include <math.h>

#define NB 4
#define NC 64
#define NO 64
#define NH 128
#define NW 128
#define HW (NH*NW)

// Scratch (static device globals — no allocation)
__device__ float  g_xT[NB*16*HW*4];     // x repacked: [b][c/4][h][w][4]
__device__ float4 g_w4[NB*9*HW];        // bilinear corner weights (mask+validity premult)
__device__ int4   g_i4[NB*9*HW];        // 4 corner element offsets (y*128+x)
__device__ float  g_Wt[9*64*64];        // weight repacked: [k][c][o]
__device__ float  g_omwT[9*64*28];      // om_weight repacked: [tap][c][j(pad28)]

// ---------------------------------------------------------------------------
// Kernel 0: NCHW -> [b][c/4][h][w][4] repack (coalesced via smem tile)
// ---------------------------------------------------------------------------
__global__ void __launch_bounds__(256) k_transpose(const float* __restrict__ x) {
    __shared__ float ts[64][33];
    int blk = blockIdx.x;
    int wc = blk & 3;
    int h  = (blk >> 2) & 127;
    int b  = blk >> 9;
    int w0 = wc * 32;
    int t = threadIdx.x;
    #pragma unroll
    for (int i = 0; i < 8; i++) {
        int idx = i * 256 + t;
        int c = idx >> 5, w = idx & 31;
        ts[c][w] = x[((b*64 + c)*NH + h)*NW + w0 + w];
    }
    __syncthreads();
    #pragma unroll
    for (int i = 0; i < 8; i++) {
        int idx = i * 256 + t;
        int comp = idx & 3, w = (idx >> 2) & 31, cg = idx >> 7;
        g_xT[((((b*16 + cg)*NH + h)*NW + w0 + w) << 2) + comp] = ts[cg*4 + comp][w];
    }
}

// ---------------------------------------------------------------------------
// Kernel R: weight reorganizations.
// ---------------------------------------------------------------------------
__global__ void __launch_bounds__(256) k_reorg(const float* __restrict__ wgt,
                                               const float* __restrict__ omw) {
    int i = blockIdx.x * 256 + threadIdx.x;
    if (i < 9*64*64) {              // g_Wt[k][c][o] = weight[o][c][k]
        int o = i & 63, c = (i >> 6) & 63, k = i >> 12;
        g_Wt[i] = wgt[(o*64 + c)*9 + k];
    }
    if (i < 9*64*28) {              // g_omwT[tap][c][j] = om_weight[j][c][tap]
        int j = i % 28;
        int c = (i / 28) & 63;
        int tap = i / (28*64);
        g_omwT[i] = (j < 27) ? omw[(j*64 + c)*9 + tap] : 0.f;
    }
}

// ---------------------------------------------------------------------------
// Metadata builder: from (py, px, mask) produce premultiplied corner weights
// and clamped corner element offsets.
// ---------------------------------------------------------------------------
__device__ __forceinline__ void make_meta(float py, float pxx, float m,
                                          float4& w4, int4& i4) {
    float y0f = floorf(py), x0f = floorf(pxx);
    float wy = py - y0f, wx = pxx - x0f;
    bool vy0 = (y0f >=  0.f) && (y0f <= 127.f);
    bool vy1 = (y0f >= -1.f) && (y0f <= 126.f);
    bool vx0 = (x0f >=  0.f) && (x0f <= 127.f);
    bool vx1 = (x0f >= -1.f) && (x0f <= 126.f);
    int iy0 = (int)fminf(fmaxf(y0f,       0.f), 127.f);
    int iy1 = (int)fminf(fmaxf(y0f + 1.f, 0.f), 127.f);
    int ix0 = (int)fminf(fmaxf(x0f,       0.f), 127.f);
    int ix1 = (int)fminf(fmaxf(x0f + 1.f, 0.f), 127.f);
    w4.x = (1.f-wy)*(1.f-wx) * ((vy0 && vx0) ? m : 0.f);
    w4.y = (1.f-wy)*wx       * ((vy0 && vx1) ? m : 0.f);
    w4.z = wy*(1.f-wx)       * ((vy1 && vx0) ? m : 0.f);
    w4.w = wy*wx             * ((vy1 && vx1) ? m : 0.f);
    i4.x = iy0*NW + ix0;
    i4.y = iy0*NW + ix1;
    i4.z = iy1*NW + ix0;
    i4.w = iy1*NW + ix1;
}

// ---------------------------------------------------------------------------
// Kernel 1: offset/mask conv (64 -> 27ch 3x3) + full gather-metadata build.
// 2 horizontally adjacent pixels per thread. 128 blocks x 256 threads.
// ---------------------------------------------------------------------------
__global__ void __launch_bounds__(256) k_offsets(const float* __restrict__ om_bias) {
    extern __shared__ float wsm[];      // [tap][c][28]
    int t = threadIdx.x;
    for (int i = t; i < 9*64*28; i += 256) wsm[i] = g_omwT[i];
    __syncthreads();

    int lin = blockIdx.x * 256 + t;     // 0..32767 (pixel pairs)
    int w0 = (lin & 63) * 2;
    int h  = (lin >> 6) & 127;
    int b  = lin >> 13;

    float4 acc0[7], acc1[7];
    #pragma unroll
    for (int j4 = 0; j4 < 7; j4++) {
        float bv[4];
        #pragma unroll
        for (int q = 0; q < 4; q++) {
            int j = j4*4 + q;
            bv[q] = (j < 27) ? __ldg(om_bias + j) : 0.f;
        }
        acc0[j4] = make_float4(bv[0], bv[1], bv[2], bv[3]);
        acc1[j4] = acc0[j4];
    }

    #pragma unroll
    for (int tap = 0; tap < 9; tap++) {
        int ny  = h + tap/3 - 1;
        int nx0 = w0 + tap%3 - 1;
        bool vy = (ny >= 0) && (ny < NH);
        bool v0 = vy && (nx0 >= 0) && (nx0 < NW);
        bool v1 = vy && (nx0 + 1 >= 0) && (nx0 + 1 < NW);
        #pragma unroll
        for (int cg = 0; cg < 16; cg++) {
            float4 p0 = make_float4(0.f,0.f,0.f,0.f);
            float4 p1 = make_float4(0.f,0.f,0.f,0.f);
            if (v0) p0 = *(const float4*)(g_xT + ((((b*16 + cg)*NH + ny)*NW + nx0) << 2));
            if (v1) p1 = *(const float4*)(g_xT + ((((b*16 + cg)*NH + ny)*NW + nx0 + 1) << 2));
            float p0a[4], p1a[4];
            *(float4*)p0a = p0; *(float4*)p1a = p1;
            const float* wr = &wsm[(tap*64 + cg*4)*28];
            #pragma unroll
            for (int ci = 0; ci < 4; ci++) {
                float a0 = p0a[ci], a1 = p1a[ci];
                #pragma unroll
                for (int j4 = 0; j4 < 7; j4++) {
                    float4 w4 = *(const float4*)(wr + ci*28 + j4*4);
                    acc0[j4].x += a0*w4.x; acc0[j4].y += a0*w4.y;
                    acc0[j4].z += a0*w4.z; acc0[j4].w += a0*w4.w;
                    acc1[j4].x += a1*w4.x; acc1[j4].y += a1*w4.y;
                    acc1[j4].z += a1*w4.z; acc1[j4].w += a1*w4.w;
                }
            }
        }
    }

    float o0[28], o1[28];
    #pragma unroll
    for (int j4 = 0; j4 < 7; j4++) {
        ((float4*)o0)[j4] = acc0[j4];
        ((float4*)o1)[j4] = acc1[j4];
    }

    #pragma unroll
    for (int k = 0; k < 9; k++) {
        int base = (b*9 + k)*HW + h*NW + w0;
        float ky = (float)(k/3), kx = (float)(k%3);
        float m0 = 1.f / (1.f + expf(-o0[18+k]));
        float m1 = 1.f / (1.f + expf(-o1[18+k]));
        float4 w4; int4 i4;
        make_meta(o0[2*k] + ky + (float)(h - 1),
                  o0[2*k+1] + kx + (float)(w0 - 1), m0, w4, i4);
        g_w4[base] = w4; g_i4[base] = i4;
        make_meta(o1[2*k] + ky + (float)(h - 1),
                  o1[2*k+1] + kx + (float)(w0), m1, w4, i4);
        g_w4[base + 1] = w4; g_i4[base + 1] = i4;
    }
}

// ---------------------------------------------------------------------------
// Kernel 2: bilinear sampling + output GEMM.
// One block per (b,h) row: 512 blocks x 256 threads, 3 CTAs/SM.
// Each thread owns one px (t&127) for gathering; cg = it*2 + (t>>7).
// ---------------------------------------------------------------------------
__global__ void __launch_bounds__(256, 3) k_main(const float* __restrict__ bias,
                                                 float* __restrict__ out) {
    __shared__ float ssamp[64*128];     // 32 KB: [c][px]
    int t = threadIdx.x;
    int blk = blockIdx.x;
    int h = blk & 127;
    int b = blk >> 7;
    int px  = t & 127;
    int cg0 = t >> 7;                   // 0 or 1
    int o_base  = (t >> 5) * 8;
    int px_base = (t & 31) * 4;

    const float4* xb = (const float4*)g_xT + (size_t)(b*16)*HW;
    int mi = (b*9)*HW + h*NW + px;

    float4 acc[8];
    #pragma unroll
    for (int i = 0; i < 8; i++) acc[i] = make_float4(0.f,0.f,0.f,0.f);

    for (int k = 0; k < 9; k++) {
        float4 wq = __ldg(g_w4 + mi);
        int4   iq = __ldg(g_i4 + mi);
        mi += HW;
        __syncthreads();
        // ---- phase A: gather + bilinear blend into ssamp ----
        #pragma unroll
        for (int it = 0; it < 8; it++) {
            int cg = it*2 + cg0;
            const float4* cb = xb + (size_t)cg*HW;
            float4 A  = __ldg(cb + iq.x);
            float4 Bc = __ldg(cb + iq.y);
            float4 Cc = __ldg(cb + iq.z);
            float4 D  = __ldg(cb + iq.w);
            int sb = (cg*4)*128 + px;
            ssamp[sb]       = wq.x*A.x + wq.y*Bc.x + wq.z*Cc.x + wq.w*D.x;
            ssamp[sb + 128] = wq.x*A.y + wq.y*Bc.y + wq.z*Cc.y + wq.w*D.y;
            ssamp[sb + 256] = wq.x*A.z + wq.y*Bc.z + wq.z*Cc.z + wq.w*D.z;
            ssamp[sb + 384] = wq.x*A.w + wq.y*Bc.w + wq.z*Cc.w + wq.w*D.w;
        }
        __syncthreads();
        // ---- phase B: out[o] += W[k][c][o] * samp[c][px] ----
        const float* wk = g_Wt + k*4096 + o_base;
        #pragma unroll 4
        for (int c = 0; c < 64; c++) {
            float4 wlo = __ldg((const float4*)(wk + c*64));
            float4 whi = __ldg((const float4*)(wk + c*64 + 4));
            float4 s4  = *(const float4*)(ssamp + c*128 + px_base);
            float wv[8] = {wlo.x, wlo.y, wlo.z, wlo.w, whi.x, whi.y, whi.z, whi.w};
            #pragma unroll
            for (int oi = 0; oi < 8; oi++) {
                acc[oi].x += wv[oi]*s4.x;
                acc[oi].y += wv[oi]*s4.y;
                acc[oi].z += wv[oi]*s4.z;
                acc[oi].w += wv[oi]*s4.w;
            }
        }
    }

    #pragma unroll
    for (int oi = 0; oi < 8; oi++) {
        float bv = __ldg(bias + o_base + oi);
        float4 r = acc[oi];
        r.x += bv; r.y += bv; r.z += bv; r.w += bv;
        *(float4*)(out + (((b*64 + o_base + oi)*NH + h)*NW) + px_base) = r;
    }
}

// ---------------------------------------------------------------------------
extern "C" void kernel_launch(void* const* d_in, const int* in_sizes, int n_in,
                              void* d_out, int out_size) {
    const float* x         = (const float*)d_in[0];
    const float* weight    = (const float*)d_in[1];
    const float* bias      = (const float*)d_in[2];
    const float* om_weight = (const float*)d_in[3];
    const float* om_bias   = (const float*)d_in[4];
    float* out = (float*)d_out;

    cudaFuncSetAttribute(k_offsets, cudaFuncAttributeMaxDynamicSharedMemorySize, 9*64*28*4);

    k_transpose<<<2048, 256>>>(x);
    k_reorg<<<144, 256>>>(weight, om_weight);
    k_offsets<<<128, 256, 9*64*28*4>>>(om_bias);
    k_main<<<512, 256>>>(bias, out);
}

// round 3
// speedup vs baseline: 1.1238x; 1.1238x over previous
#include <cuda_runtime.h>
#include <math.h>

#define NB 4
#define NC 64
#define NO 64
#define NH 128
#define NW 128
#define HW (NH*NW)

// Scratch (static device globals — no allocation)
__device__ float g_xT[NB*16*HW*4];      // x repacked: [b][c/4][h][w][4]
__device__ float g_py[NB*9*HW];         // sample y coord per (b,k,h,w)
__device__ float g_px[NB*9*HW];         // sample x coord
__device__ float g_ms[NB*9*HW];         // sigmoid(mask)
__device__ float g_Wt[9*64*64];         // weight repacked: [k][c][o]
__device__ float g_omwT[9*64*28];       // om_weight repacked: [tap][c][j(pad28)]

// ---------------------------------------------------------------------------
// Kernel 0: NCHW -> [b][c/4][h][w][4] repack (coalesced via smem tile)
// ---------------------------------------------------------------------------
__global__ void __launch_bounds__(256) k_transpose(const float* __restrict__ x) {
    __shared__ float ts[64][33];
    int blk = blockIdx.x;
    int wc = blk & 3;
    int h  = (blk >> 2) & 127;
    int b  = blk >> 9;
    int w0 = wc * 32;
    int t = threadIdx.x;
    #pragma unroll
    for (int i = 0; i < 8; i++) {
        int idx = i * 256 + t;
        int c = idx >> 5, w = idx & 31;
        ts[c][w] = x[((b*64 + c)*NH + h)*NW + w0 + w];
    }
    __syncthreads();
    #pragma unroll
    for (int i = 0; i < 8; i++) {
        int idx = i * 256 + t;
        int comp = idx & 3, w = (idx >> 2) & 31, cg = idx >> 7;
        g_xT[((((b*16 + cg)*NH + h)*NW + w0 + w) << 2) + comp] = ts[cg*4 + comp][w];
    }
}

// ---------------------------------------------------------------------------
// Kernel R: weight reorganizations.
// ---------------------------------------------------------------------------
__global__ void __launch_bounds__(256) k_reorg(const float* __restrict__ wgt,
                                               const float* __restrict__ omw) {
    int i = blockIdx.x * 256 + threadIdx.x;
    if (i < 9*64*64) {              // g_Wt[k][c][o] = weight[o][c][k]
        int o = i & 63, c = (i >> 6) & 63, k = i >> 12;
        g_Wt[i] = wgt[(o*64 + c)*9 + k];
    }
    if (i < 9*64*28) {              // g_omwT[tap][c][j] = om_weight[j][c][tap]
        int j = i % 28;
        int c = (i / 28) & 63;
        int tap = i / (28*64);
        g_omwT[i] = (j < 27) ? omw[(j*64 + c)*9 + tap] : 0.f;
    }
}

// ---------------------------------------------------------------------------
// Kernel 1: offset/mask conv (64 -> 27ch 3x3). Writes py/px/ms only.
// ---------------------------------------------------------------------------
__global__ void __launch_bounds__(256) k_offsets(const float* __restrict__ om_bias) {
    extern __shared__ float wsm[];      // [tap][c][28]
    int t = threadIdx.x;
    for (int i = t; i < 9*64*28; i += 256) wsm[i] = g_omwT[i];
    __syncthreads();

    int lin = blockIdx.x * 256 + t;     // 0..32767 (pixel pairs)
    int w0 = (lin & 63) * 2;
    int h  = (lin >> 6) & 127;
    int b  = lin >> 13;

    float4 acc0[7], acc1[7];
    #pragma unroll
    for (int j4 = 0; j4 < 7; j4++) {
        float bv[4];
        #pragma unroll
        for (int q = 0; q < 4; q++) {
            int j = j4*4 + q;
            bv[q] = (j < 27) ? __ldg(om_bias + j) : 0.f;
        }
        acc0[j4] = make_float4(bv[0], bv[1], bv[2], bv[3]);
        acc1[j4] = acc0[j4];
    }

    #pragma unroll
    for (int tap = 0; tap < 9; tap++) {
        int ny  = h + tap/3 - 1;
        int nx0 = w0 + tap%3 - 1;
        bool vy = (ny >= 0) && (ny < NH);
        bool v0 = vy && (nx0 >= 0) && (nx0 < NW);
        bool v1 = vy && (nx0 + 1 >= 0) && (nx0 + 1 < NW);
        #pragma unroll
        for (int cg = 0; cg < 16; cg++) {
            float4 p0 = make_float4(0.f,0.f,0.f,0.f);
            float4 p1 = make_float4(0.f,0.f,0.f,0.f);
            if (v0) p0 = *(const float4*)(g_xT + ((((b*16 + cg)*NH + ny)*NW + nx0) << 2));
            if (v1) p1 = *(const float4*)(g_xT + ((((b*16 + cg)*NH + ny)*NW + nx0 + 1) << 2));
            float p0a[4], p1a[4];
            *(float4*)p0a = p0; *(float4*)p1a = p1;
            const float* wr = &wsm[(tap*64 + cg*4)*28];
            #pragma unroll
            for (int ci = 0; ci < 4; ci++) {
                float a0 = p0a[ci], a1 = p1a[ci];
                #pragma unroll
                for (int j4 = 0; j4 < 7; j4++) {
                    float4 w4 = *(const float4*)(wr + ci*28 + j4*4);
                    acc0[j4].x += a0*w4.x; acc0[j4].y += a0*w4.y;
                    acc0[j4].z += a0*w4.z; acc0[j4].w += a0*w4.w;
                    acc1[j4].x += a1*w4.x; acc1[j4].y += a1*w4.y;
                    acc1[j4].z += a1*w4.z; acc1[j4].w += a1*w4.w;
                }
            }
        }
    }

    float o0[28], o1[28];
    #pragma unroll
    for (int j4 = 0; j4 < 7; j4++) {
        ((float4*)o0)[j4] = acc0[j4];
        ((float4*)o1)[j4] = acc1[j4];
    }

    #pragma unroll
    for (int k = 0; k < 9; k++) {
        int off = ((b*9 + k)*NH + h)*NW + w0;
        float ky = (float)(k/3), kx = (float)(k%3);
        g_py[off]     = o0[2*k]   + ky + (float)(h - 1);
        g_py[off + 1] = o1[2*k]   + ky + (float)(h - 1);
        g_px[off]     = o0[2*k+1] + kx + (float)(w0 - 1);
        g_px[off + 1] = o1[2*k+1] + kx + (float)(w0);
        g_ms[off]     = 1.f / (1.f + expf(-o0[18+k]));
        g_ms[off + 1] = 1.f / (1.f + expf(-o1[18+k]));
    }
}

// ---------------------------------------------------------------------------
// Gather one tap's 64c x 64px tile into smem buf (bilinear blend).
// Meta computed once per thread (px fixed), reused across the 4 cg iters.
// ---------------------------------------------------------------------------
__device__ __forceinline__ void gather_tap(const float4* __restrict__ xb,
                                           int mi, int px, int cg0,
                                           float* __restrict__ buf) {
    float py  = __ldg(g_py + mi);
    float pxx = __ldg(g_px + mi);
    float m   = __ldg(g_ms + mi);
    float y0f = floorf(py), x0f = floorf(pxx);
    float wy = py - y0f, wx = pxx - x0f;
    bool vy0 = (y0f >=  0.f) && (y0f <= 127.f);
    bool vy1 = (y0f >= -1.f) && (y0f <= 126.f);
    bool vx0 = (x0f >=  0.f) && (x0f <= 127.f);
    bool vx1 = (x0f >= -1.f) && (x0f <= 126.f);
    int iy0 = (int)fminf(fmaxf(y0f,       0.f), 127.f);
    int iy1 = (int)fminf(fmaxf(y0f + 1.f, 0.f), 127.f);
    int ix0 = (int)fminf(fmaxf(x0f,       0.f), 127.f);
    int ix1 = (int)fminf(fmaxf(x0f + 1.f, 0.f), 127.f);
    float w00 = (1.f-wy)*(1.f-wx) * ((vy0 && vx0) ? m : 0.f);
    float w01 = (1.f-wy)*wx       * ((vy0 && vx1) ? m : 0.f);
    float w10 = wy*(1.f-wx)       * ((vy1 && vx0) ? m : 0.f);
    float w11 = wy*wx             * ((vy1 && vx1) ? m : 0.f);
    int i00 = iy0*NW + ix0, i01 = iy0*NW + ix1;
    int i10 = iy1*NW + ix0, i11 = iy1*NW + ix1;
    #pragma unroll
    for (int it = 0; it < 4; it++) {
        int cg = it*4 + cg0;
        const float4* cb = xb + (size_t)cg*HW;
        float4 A  = __ldg(cb + i00);
        float4 Bc = __ldg(cb + i01);
        float4 Cc = __ldg(cb + i10);
        float4 D  = __ldg(cb + i11);
        int sb = (cg*4)*64 + px;
        buf[sb]       = w00*A.x + w01*Bc.x + w10*Cc.x + w11*D.x;
        buf[sb +  64] = w00*A.y + w01*Bc.y + w10*Cc.y + w11*D.y;
        buf[sb + 128] = w00*A.z + w01*Bc.z + w10*Cc.z + w11*D.z;
        buf[sb + 192] = w00*A.w + w01*Bc.w + w10*Cc.w + w11*D.w;
    }
}

// ---------------------------------------------------------------------------
// Kernel 2: bilinear sampling + output GEMM, software-pipelined over taps.
// One block per (b,h,half-row): 1024 blocks x 256 threads.
// Tile: samp[64c][64px] double-buffered (2 x 16KB smem).
// Per tap: GEMM on buf[k&1] while gathering tap k+1 into buf[(k+1)&1];
// ONE __syncthreads per tap.
// GEMM register tile: 4o x 4px per thread (64o x 64px total).
// ---------------------------------------------------------------------------
__global__ void __launch_bounds__(256) k_main(const float* __restrict__ bias,
                                              float* __restrict__ out) {
    extern __shared__ float ssamp[];    // [2][64*64]
    int t = threadIdx.x;
    int blk = blockIdx.x;
    int half = blk & 1;
    int h = (blk >> 1) & 127;
    int b = blk >> 8;
    int w0 = half * 64;

    int px  = t & 63;                   // gather: pixel owned (local)
    int cg0 = t >> 6;                   // 0..3
    int o_base  = (t >> 4) * 4;         // GEMM: 4 outputs
    int px_base = (t & 15) * 4;         // GEMM: 4 pixels (local)

    const float4* xb = (const float4*)g_xT + (size_t)(b*16)*HW;
    int offm = (b*9)*HW + h*NW + w0 + px;

    float4 acc[4];
    #pragma unroll
    for (int i = 0; i < 4; i++) acc[i] = make_float4(0.f,0.f,0.f,0.f);

    // prologue: gather tap 0 into buf 0
    gather_tap(xb, offm, px, cg0, ssamp);
    __syncthreads();

    for (int k = 0; k < 9; k++) {
        const float* buf = ssamp + (k & 1) * 4096;
        const float* wk = g_Wt + k*4096 + o_base;
        #pragma unroll 8
        for (int c = 0; c < 64; c++) {
            float4 wv = __ldg((const float4*)(wk + c*64));
            float4 s4 = *(const float4*)(buf + c*64 + px_base);
            acc[0].x += wv.x*s4.x; acc[0].y += wv.x*s4.y; acc[0].z += wv.x*s4.z; acc[0].w += wv.x*s4.w;
            acc[1].x += wv.y*s4.x; acc[1].y += wv.y*s4.y; acc[1].z += wv.y*s4.z; acc[1].w += wv.y*s4.w;
            acc[2].x += wv.z*s4.x; acc[2].y += wv.z*s4.y; acc[2].z += wv.z*s4.z; acc[2].w += wv.z*s4.w;
            acc[3].x += wv.w*s4.x; acc[3].y += wv.w*s4.y; acc[3].z += wv.w*s4.z; acc[3].w += wv.w*s4.w;
        }
        if (k < 8)
            gather_tap(xb, offm + (k+1)*HW, px, cg0, ssamp + ((k+1) & 1) * 4096);
        __syncthreads();
    }

    #pragma unroll
    for (int oi = 0; oi < 4; oi++) {
        float bv = __ldg(bias + o_base + oi);
        float4 r = acc[oi];
        r.x += bv; r.y += bv; r.z += bv; r.w += bv;
        *(float4*)(out + (((b*64 + o_base + oi)*NH + h)*NW) + w0 + px_base) = r;
    }
}

// ---------------------------------------------------------------------------
extern "C" void kernel_launch(void* const* d_in, const int* in_sizes, int n_in,
                              void* d_out, int out_size) {
    const float* x         = (const float*)d_in[0];
    const float* weight    = (const float*)d_in[1];
    const float* bias      = (const float*)d_in[2];
    const float* om_weight = (const float*)d_in[3];
    const float* om_bias   = (const float*)d_in[4];
    float* out = (float*)d_out;

    cudaFuncSetAttribute(k_offsets, cudaFuncAttributeMaxDynamicSharedMemorySize, 9*64*28*4);

    k_transpose<<<2048, 256>>>(x);
    k_reorg<<<144, 256>>>(weight, om_weight);
    k_offsets<<<128, 256, 9*64*28*4>>>(om_bias);
    k_main<<<1024, 256, 2*64*64*4>>>(bias, out);
}